// round 1
// baseline (speedup 1.0000x reference)
#include <cuda_runtime.h>
#include <math.h>

#define LN_EPS 1e-5f

// ---------------- scratch (device globals: no allocation allowed) ----------------
__device__ float g_CB0[128 * 512];     // codebook @ mla_w0
__device__ float g_MP0[64 * 512];      // map_pos_embed @ mla_w0
__device__ float g_AP0[8192 * 512];    // agent_pos_embed @ mla_w0 + mla_b0

// block-wide (128 threads) reduction of two floats; leaves result in s/s2 for all threads
__device__ __forceinline__ void blockReduce2_128(float& s, float& s2, float* red) {
#pragma unroll
    for (int off = 16; off > 0; off >>= 1) {
        s  += __shfl_xor_sync(0xffffffffu, s,  off);
        s2 += __shfl_xor_sync(0xffffffffu, s2, off);
    }
    int w = threadIdx.x >> 5;
    if ((threadIdx.x & 31) == 0) { red[w] = s; red[4 + w] = s2; }
    __syncthreads();
    s  = red[0] + red[1] + red[2] + red[3];
    s2 = red[4] + red[5] + red[6] + red[7];
    __syncthreads();
}

// ---------------- kernel 1: map_pos_embed MLP + projection through mla_w0 ----------------
// grid 64 (one per map position m), 128 threads
__global__ __launch_bounds__(128) void k_mp(
    const float* __restrict__ mpl,                 // [64,256]
    const float* __restrict__ w0, const float* __restrict__ b0,
    const float* __restrict__ g0, const float* __restrict__ t0,
    const float* __restrict__ w1, const float* __restrict__ b1,
    const float* __restrict__ W0mla)               // [128,512]
{
    __shared__ float xs[256];
    __shared__ float hs[128];
    __shared__ float mp[128];
    __shared__ float red[8];
    int m = blockIdx.x, j = threadIdx.x;
    xs[j]       = mpl[m * 256 + j];
    xs[128 + j] = mpl[m * 256 + 128 + j];
    __syncthreads();

    float z = b0[j];
#pragma unroll 8
    for (int i = 0; i < 256; i++) z = fmaf(xs[i], w0[i * 128 + j], z);
    float s = z, s2 = z * z;
    blockReduce2_128(s, s2, red);
    float mean = s * (1.f / 128.f);
    float var  = s2 * (1.f / 128.f) - mean * mean;
    float rs   = rsqrtf(var + LN_EPS);
    hs[j] = fmaxf((z - mean) * rs * g0[j] + t0[j], 0.f);
    __syncthreads();

    float z1 = b1[j];
#pragma unroll 8
    for (int i = 0; i < 128; i++) z1 = fmaf(hs[i], w1[i * 128 + j], z1);
    mp[j] = z1;
    __syncthreads();

#pragma unroll
    for (int q = 0; q < 4; q++) {
        int c = j + q * 128;
        float acc = 0.f;
#pragma unroll 8
        for (int i = 0; i < 128; i++) acc = fmaf(mp[i], W0mla[i * 512 + c], acc);
        g_MP0[m * 512 + c] = acc;
    }
}

// ---------------- kernel 2: codebook @ mla_w0 ----------------
// grid 128 (one per codebook row), 128 threads
__global__ __launch_bounds__(128) void k_cb(
    const float* __restrict__ tok,                 // [128,128]
    const float* __restrict__ W0mla)               // [128,512]
{
    __shared__ float cb[128];
    int lat = blockIdx.x, j = threadIdx.x;
    cb[j] = tok[lat * 128 + j];
    __syncthreads();
#pragma unroll
    for (int q = 0; q < 4; q++) {
        int c = j + q * 128;
        float acc = 0.f;
#pragma unroll 8
        for (int i = 0; i < 128; i++) acc = fmaf(cb[i], W0mla[i * 512 + c], acc);
        g_CB0[lat * 512 + c] = acc;
    }
}

// ---------------- kernel 3: agent_pos_emb MLP + projection, fold mla_b0 ----------------
// grid 8192 = bs*T, 128 threads
__global__ __launch_bounds__(128) void k_ape(
    const float* __restrict__ heading,             // [64,32,128]
    const float* __restrict__ position,            // [64,32,128,2]
    const float* __restrict__ w0, const float* __restrict__ b0,
    const float* __restrict__ g0, const float* __restrict__ t0,
    const float* __restrict__ w1, const float* __restrict__ b1,
    const float* __restrict__ g1, const float* __restrict__ t1,
    const float* __restrict__ w2, const float* __restrict__ b2,
    const float* __restrict__ W0mla, const float* __restrict__ b0mla)
{
    __shared__ float a1[128], a2[128], av[128], red[8];
    int bt = blockIdx.x;
    int b = bt >> 7, t = bt & 127;
    int j = threadIdx.x;

    float hd = heading[(b * 32) * 128 + t];
    float px = position[((b * 32) * 128 + t) * 2 + 0];
    float py = position[((b * 32) * 128 + t) * 2 + 1];
    float sh = sinf(hd), ch = cosf(hd);

    float z = b0[j];
    z = fmaf(px, w0[0 * 128 + j], z);
    z = fmaf(py, w0[1 * 128 + j], z);
    z = fmaf(hd, w0[2 * 128 + j], z);
    z = fmaf(sh, w0[3 * 128 + j], z);
    z = fmaf(ch, w0[4 * 128 + j], z);
    float s = z, s2 = z * z;
    blockReduce2_128(s, s2, red);
    float mean = s * (1.f / 128.f);
    float var  = s2 * (1.f / 128.f) - mean * mean;
    float rs   = rsqrtf(var + LN_EPS);
    a1[j] = fmaxf((z - mean) * rs * g0[j] + t0[j], 0.f);
    __syncthreads();

    float z1 = b1[j];
#pragma unroll 8
    for (int i = 0; i < 128; i++) z1 = fmaf(a1[i], w1[i * 128 + j], z1);
    s = z1; s2 = z1 * z1;
    blockReduce2_128(s, s2, red);
    mean = s * (1.f / 128.f);
    var  = s2 * (1.f / 128.f) - mean * mean;
    rs   = rsqrtf(var + LN_EPS);
    a2[j] = fmaxf((z1 - mean) * rs * g1[j] + t1[j], 0.f);
    __syncthreads();

    float z2 = b2[j];
#pragma unroll 8
    for (int i = 0; i < 128; i++) z2 = fmaf(a2[i], w2[i * 128 + j], z2);
    av[j] = z2;
    __syncthreads();

#pragma unroll
    for (int q = 0; q < 4; q++) {
        int c = j + q * 128;
        float acc = b0mla[c];
#pragma unroll 8
        for (int i = 0; i < 128; i++) acc = fmaf(av[i], W0mla[i * 512 + c], acc);
        g_AP0[bt * 512 + c] = acc;
    }
}

// ---------------- kernel 4: fused gather + LN + ReLU + GEMM (the 34.4 GMAC) ----------------
// grid 8192 (one per (b,t): exactly the 64 m-rows), 256 threads
// smem layout (floats): Hs[64*514] | Wp[64*128 packed pairs] | Aps[512] | gsm[512] | tsm[512]
#define S_H 514
#define SMEM_FLOATS (64 * S_H + 64 * 128 + 512 * 3)
#define SMEM_BYTES (SMEM_FLOATS * 4)

__device__ __forceinline__ void fma2(unsigned long long& d, unsigned long long a, unsigned long long b) {
    asm("fma.rn.f32x2 %0, %1, %2, %0;" : "+l"(d) : "l"(a), "l"(b));
}

__global__ __launch_bounds__(256) void k_main(
    const int* __restrict__ lat_idx,               // [64,128,64]
    const float* __restrict__ W1,                  // [512,128]
    const float* __restrict__ b1,                  // [128]
    const float* __restrict__ g0, const float* __restrict__ t0,  // [512]
    float* __restrict__ out)                       // [64,128,64,128]
{
    extern __shared__ float smem[];
    float* Hs  = smem;
    float* wp  = smem + 64 * S_H;
    float* Aps = wp + 64 * 128;
    float* gsm = Aps + 512;
    float* tsm = gsm + 512;

    int bt  = blockIdx.x;
    int tid = threadIdx.x;
    int w = tid >> 5, l = tid & 31;

    for (int i = tid; i < 512; i += 256) {
        Aps[i] = g_AP0[bt * 512 + i];
        gsm[i] = g0[i];
        tsm[i] = t0[i];
    }
    __syncthreads();

    // -------- phase 1: build H tile (64 rows x 512), each warp does 8 rows --------
#pragma unroll
    for (int mm = 0; mm < 8; mm++) {
        int m = w * 8 + mm;
        int lat = lat_idx[bt * 64 + m];
        const float* cb = g_CB0 + lat * 512;
        const float* mp = g_MP0 + m * 512;
        float y[16];
        float s = 0.f, s2 = 0.f;
#pragma unroll
        for (int q = 0; q < 16; q++) {
            int k = q * 32 + l;
            float v = cb[k] + mp[k] + Aps[k];
            y[q] = v; s += v; s2 += v * v;
        }
#pragma unroll
        for (int off = 16; off > 0; off >>= 1) {
            s  += __shfl_xor_sync(0xffffffffu, s,  off);
            s2 += __shfl_xor_sync(0xffffffffu, s2, off);
        }
        float mean = s * (1.f / 512.f);
        float var  = s2 * (1.f / 512.f) - mean * mean;
        float rs   = rsqrtf(var + LN_EPS);
#pragma unroll
        for (int q = 0; q < 16; q++) {
            int k = q * 32 + l;
            float h = (y[q] - mean) * rs * gsm[k] + tsm[k];
            Hs[m * S_H + k] = fmaxf(h, 0.f);
        }
    }
    __syncthreads();

    // -------- phase 2: H[64,512] @ W1[512,128] with packed f32x2 FMA --------
    int ty = tid >> 4;   // 0..15 -> rows 4*ty .. 4*ty+3
    int tx = tid & 15;   // cols tx + 16*q, q<8

    unsigned long long acc[4][8];
#pragma unroll
    for (int r = 0; r < 4; r++)
#pragma unroll
        for (int q = 0; q < 8; q++) acc[r][q] = 0ull;

    for (int kc = 0; kc < 8; kc++) {
        const float* Wg = W1 + kc * 64 * 128;
        // pack W chunk: wp pair (k even, k odd) per (k2, c)
        for (int idx = tid; idx < 32 * 128; idx += 256) {
            int k2 = idx >> 7, c = idx & 127;
            wp[idx * 2 + 0] = Wg[(2 * k2) * 128 + c];
            wp[idx * 2 + 1] = Wg[(2 * k2 + 1) * 128 + c];
        }
        __syncthreads();

        const float* hbase = Hs + kc * 64;
#pragma unroll
        for (int k2 = 0; k2 < 32; k2++) {
            unsigned long long aa[4], bb[8];
#pragma unroll
            for (int r = 0; r < 4; r++)
                aa[r] = *reinterpret_cast<const unsigned long long*>(&hbase[(4 * ty + r) * S_H + 2 * k2]);
#pragma unroll
            for (int q = 0; q < 8; q++)
                bb[q] = *reinterpret_cast<const unsigned long long*>(&wp[(k2 * 128 + tx + 16 * q) * 2]);
#pragma unroll
            for (int r = 0; r < 4; r++)
#pragma unroll
                for (int q = 0; q < 8; q++) fma2(acc[r][q], aa[r], bb[q]);
        }
        __syncthreads();
    }

    // -------- epilogue --------
#pragma unroll
    for (int r = 0; r < 4; r++) {
        int row = bt * 64 + 4 * ty + r;
#pragma unroll
        for (int q = 0; q < 8; q++) {
            int c = tx + 16 * q;
            unsigned long long u = acc[r][q];
            float lo = __uint_as_float((unsigned)u);
            float hi = __uint_as_float((unsigned)(u >> 32));
            out[row * 128 + c] = lo + hi + b1[c];
        }
    }
}

// ---------------- launch ----------------
extern "C" void kernel_launch(void* const* d_in, const int* in_sizes, int n_in,
                              void* d_out, int out_size) {
    const int*   map_latent = (const int*)d_in[0];
    const float* heading    = (const float*)d_in[1];
    const float* position   = (const float*)d_in[2];
    const float* tokenizer  = (const float*)d_in[3];
    const float* mpl        = (const float*)d_in[4];
    const float* ape_w0 = (const float*)d_in[5];
    const float* ape_b0 = (const float*)d_in[6];
    const float* ape_g0 = (const float*)d_in[7];
    const float* ape_t0 = (const float*)d_in[8];
    const float* ape_w1 = (const float*)d_in[9];
    const float* ape_b1 = (const float*)d_in[10];
    const float* ape_g1 = (const float*)d_in[11];
    const float* ape_t1 = (const float*)d_in[12];
    const float* ape_w2 = (const float*)d_in[13];
    const float* ape_b2 = (const float*)d_in[14];
    const float* mla_w0 = (const float*)d_in[15];
    const float* mla_b0 = (const float*)d_in[16];
    const float* mla_g0 = (const float*)d_in[17];
    const float* mla_t0 = (const float*)d_in[18];
    const float* mla_w1 = (const float*)d_in[19];
    const float* mla_b1 = (const float*)d_in[20];
    const float* mpm_w0 = (const float*)d_in[21];
    const float* mpm_b0 = (const float*)d_in[22];
    const float* mpm_g0 = (const float*)d_in[23];
    const float* mpm_t0 = (const float*)d_in[24];
    const float* mpm_w1 = (const float*)d_in[25];
    const float* mpm_b1 = (const float*)d_in[26];
    float* out = (float*)d_out;

    cudaFuncSetAttribute(k_main, cudaFuncAttributeMaxDynamicSharedMemorySize, SMEM_BYTES);

    k_mp<<<64, 128>>>(mpl, mpm_w0, mpm_b0, mpm_g0, mpm_t0, mpm_w1, mpm_b1, mla_w0);
    k_cb<<<128, 128>>>(tokenizer, mla_w0);
    k_ape<<<8192, 128>>>(heading, position,
                         ape_w0, ape_b0, ape_g0, ape_t0,
                         ape_w1, ape_b1, ape_g1, ape_t1,
                         ape_w2, ape_b2, mla_w0, mla_b0);
    k_main<<<8192, 256, SMEM_BYTES>>>(map_latent, mla_w1, mla_b1, mla_g0, mla_t0, out);
}